// round 15
// baseline (speedup 1.0000x reference)
#include <cuda_runtime.h>
#include <cuda_bf16.h>
#include <cstdint>

#define SEQ    4096
#define DM     1024
#define NOUT   864      // 12 * 72
#define NIMU   72
#define TSTEPS 300
#define PLANE  (NIMU*SEQ)   // 294912

// GEMM tiling (mma.sync m16n8k16 bf16), bulk-copy staging (R12 config)
#define BM     128
#define BN     96
#define BK     32
#define NWARP  8
#define NIT    (DM/BK)        // 32 k-chunks
#define NMB    (SEQ/BM)       // 32 m-blocks
#define NNB    (NOUT/BN)      // 9  n-blocks
#define ATILE  8192           // 128 rows x 64B
#define BTILE  6144           // 96 rows x 64B
#define STG    28672          // ahi+alo+bhi+blo per chunk
#define S_ALO  8192
#define S_BHI  16384
#define S_BLO  22528
#define NSTAGE 3
#define MB_OFF (NSTAGE*STG)               // 86016: full[0..2] then empty[0..2]
#define SMEM_TOT (NSTAGE*STG + 64)        // 86080 -> 2 CTAs/SM

typedef unsigned long long ull;

// -------- scratch: tiled+swizzled chunk layouts (bulk-copy sources) ----
// A: [mat(2)][mblk(32)][chunk(32)][128 rows x 64B]   (16 MB)
// B: [mat(2)][nblk(9)][chunk(32)][96 rows x 64B]     (3.5 MB)
__device__ __align__(16) char g_at[2 * NMB * NIT * ATILE];
__device__ __align__(16) char g_bt[2 * NNB * NIT * BTILE];
__device__ __align__(16) float g_pT[NOUT * SEQ];   // GEMM out, TRANSPOSED [n][s]

// SW64-ish swizzle on 64B-pitch rows: bits[5:4] ^= bits[8:7]
#define SWZ(b) ((b) ^ (((b) >> 3) & 0x30))

// ======================= PTX helpers ===============================
__device__ __forceinline__ uint32_t smem_to_u32(const void* p) {
    uint32_t a;
    asm("{ .reg .u64 t; cvta.to.shared.u64 t, %1; cvt.u32.u64 %0, t; }" : "=r"(a) : "l"(p));
    return a;
}
#define MBARRIER_INIT(mb, cnt) \
    asm volatile("mbarrier.init.shared.b64 [%0], %1;" :: "r"((uint32_t)(mb)), "r"((uint32_t)(cnt)) : "memory")
#define MBARRIER_EXPECT_TX(mb, tx) \
    asm volatile("mbarrier.arrive.expect_tx.shared.b64 _, [%0], %1;" \
                 :: "r"((uint32_t)(mb)), "r"((uint32_t)(tx)) : "memory")
#define MBARRIER_ARRIVE(mb) \
    asm volatile("mbarrier.arrive.shared.b64 _, [%0];" :: "r"((uint32_t)(mb)) : "memory")
#define MBARRIER_WAIT_PARITY(mb, par) do { \
    uint32_t _m = (uint32_t)(mb), _p = (uint32_t)(par), _d; \
    asm volatile("{\n\t.reg .pred p;\n\tmbarrier.try_wait.parity.acquire.cta.shared::cta.b64 p, [%1], %2;\n\tselp.b32 %0, 1, 0, p;\n\t}" \
                 : "=r"(_d) : "r"(_m), "r"(_p) : "memory"); \
    if (!_d) { \
        asm volatile("{\n\t.reg .pred P1;\n\tWL_%=:\n\tmbarrier.try_wait.parity.acquire.cta.shared::cta.b64 P1, [%0], %1, 0x989680;\n\t@P1 bra.uni WD_%=;\n\tbra.uni WL_%=;\n\tWD_%=:\n\t}" \
                     :: "r"(_m), "r"(_p) : "memory"); \
    } } while (0)
__device__ __forceinline__ void bulk_g2s(uint32_t dst, const void* src, uint32_t bytes,
                                         uint32_t mbar) {
    asm volatile("cp.async.bulk.shared::cluster.global.mbarrier::complete_tx::bytes "
                 "[%0], [%1], %2, [%3];"
                 :: "r"(dst), "l"(src), "r"(bytes), "r"(mbar) : "memory");
}
#define LDSM_X4(r0, r1, r2, r3, addr) \
    asm volatile("ldmatrix.sync.aligned.m8n8.x4.shared.b16 {%0,%1,%2,%3}, [%4];" \
                 : "=r"(r0), "=r"(r1), "=r"(r2), "=r"(r3) : "r"(addr))
#define MMA16816(d, a, b) \
    asm volatile("mma.sync.aligned.m16n8k16.row.col.f32.bf16.bf16.f32 " \
                 "{%0,%1,%2,%3}, {%4,%5,%6,%7}, {%8,%9}, {%0,%1,%2,%3};" \
                 : "+f"((d)[0]), "+f"((d)[1]), "+f"((d)[2]), "+f"((d)[3]) \
                 : "r"((a)[0]), "r"((a)[1]), "r"((a)[2]), "r"((a)[3]), \
                   "r"((b)[0]), "r"((b)[1]))

__device__ __forceinline__ ull ffma2(ull a, ull b, ull c) {
    ull d; asm("fma.rn.f32x2 %0, %1, %2, %3;" : "=l"(d) : "l"(a), "l"(b), "l"(c)); return d;
}
__device__ __forceinline__ ull fmul2(ull a, ull b) {
    ull d; asm("mul.rn.f32x2 %0, %1, %2;" : "=l"(d) : "l"(a), "l"(b)); return d;
}
__device__ __forceinline__ ull fpack2(float lo, float hi) {
    ull d; asm("mov.b64 %0, {%1, %2};" : "=l"(d) : "f"(lo), "f"(hi)); return d;
}
__device__ __forceinline__ float2 funpack2(ull v) {
    float lo, hi; asm("mov.b64 {%0, %1}, %2;" : "=f"(lo), "=f"(hi) : "l"(v));
    return make_float2(lo, hi);
}
__device__ __forceinline__ float softplusf(float x) {
    return fmaxf(x, 0.0f) + log1pf(expf(-fabsf(x)));
}
__device__ __forceinline__ uint32_t bf2u(__nv_bfloat16 a, __nv_bfloat16 b) {
    __nv_bfloat162 v; v.x = a; v.y = b;
    return *reinterpret_cast<uint32_t*>(&v);
}

// ======================= zero kinematics (split x2) ================
__global__ void zero_kernel(float* __restrict__ out) {
    int i = blockIdx.x * blockDim.x + threadIdx.x;   // PLANE/8 threads per launch
    ((float4*)out)[i] = make_float4(0.f, 0.f, 0.f, 0.f);
}

// ============== Fused LayerNorm + W-transpose ======================
// Writes bf16 hi/lo splits DIRECTLY into the tiled+swizzled chunk
// layouts consumed by the GEMM's bulk copies.
__global__ __launch_bounds__(256) void prep_kernel(const float* __restrict__ hs,
                                                   const float* __restrict__ gamma,
                                                   const float* __restrict__ beta,
                                                   const float* __restrict__ W) {
    int tid = threadIdx.x;
    if (blockIdx.x < SEQ) {
        int row = blockIdx.x;
        const float4* xr = (const float4*)(hs + (size_t)row * DM);
        float4 v = xr[tid];
        float s  = v.x + v.y + v.z + v.w;
        float ss = v.x*v.x + v.y*v.y + v.z*v.z + v.w*v.w;
        #pragma unroll
        for (int o = 16; o > 0; o >>= 1) {
            s  += __shfl_xor_sync(0xffffffffu, s,  o);
            ss += __shfl_xor_sync(0xffffffffu, ss, o);
        }
        __shared__ float2 part[8];
        __shared__ float2 mv;
        int w = tid >> 5, l = tid & 31;
        if (l == 0) part[w] = make_float2(s, ss);
        __syncthreads();
        if (tid == 0) {
            float S = 0.f, SS = 0.f;
            #pragma unroll
            for (int i = 0; i < 8; ++i) { S += part[i].x; SS += part[i].y; }
            float mu  = S * (1.0f / DM);
            float var = SS * (1.0f / DM) - mu * mu;
            mv = make_float2(mu, rsqrtf(var + 1e-5f));
        }
        __syncthreads();
        float mu = mv.x, rstd = mv.y;
        float4 g  = ((const float4*)gamma)[tid];
        float4 be = ((const float4*)beta)[tid];
        float o0 = (v.x - mu) * rstd * g.x + be.x;
        float o1 = (v.y - mu) * rstd * g.y + be.y;
        float o2 = (v.z - mu) * rstd * g.z + be.z;
        float o3 = (v.w - mu) * rstd * g.w + be.w;

        __nv_bfloat16 h0 = __float2bfloat16_rn(o0), h1 = __float2bfloat16_rn(o1);
        __nv_bfloat16 h2 = __float2bfloat16_rn(o2), h3 = __float2bfloat16_rn(o3);
        __nv_bfloat16 l0 = __float2bfloat16_rn(o0 - __bfloat162float(h0));
        __nv_bfloat16 l1 = __float2bfloat16_rn(o1 - __bfloat162float(h1));
        __nv_bfloat16 l2 = __float2bfloat16_rn(o2 - __bfloat162float(h2));
        __nv_bfloat16 l3 = __float2bfloat16_rn(o3 - __bfloat162float(h3));

        // tiled write: k = 4*tid; chunk = tid>>3; 8 bytes at swizzled slot
        int mb = row >> 7, r = row & 127;
        int ch = tid >> 3;
        uint32_t b = (uint32_t)(r * 64 + (tid & 7) * 8);
        uint32_t sw = SWZ(b);
        size_t tb_hi = ((size_t)(mb) * NIT + ch) * ATILE;
        size_t tb_lo = ((size_t)(NMB + mb) * NIT + ch) * ATILE;
        ull hv = ((ull)bf2u(h2, h3) << 32) | bf2u(h0, h1);
        ull lv = ((ull)bf2u(l2, l3) << 32) | bf2u(l0, l1);
        *(ull*)(g_at + tb_hi + sw) = hv;
        *(ull*)(g_at + tb_lo + sw) = lv;
    } else {
        __shared__ float tile[32][33];
        int b2 = blockIdx.x - SEQ;                 // 0..863 (27 x 32 tiles)
        int n0 = (b2 % 27) * 32, k0 = (b2 / 27) * 32;
        int tx = tid & 31, ty = tid >> 5;          // 32 x 8
        #pragma unroll
        for (int j = 0; j < 4; ++j)
            tile[ty + 8*j][tx] = W[(size_t)(k0 + ty + 8*j) * NOUT + n0 + tx];
        __syncthreads();
        int ch = (k0 + tx) >> 5;
        int kc = (k0 + tx) & 31;
        #pragma unroll
        for (int j = 0; j < 4; ++j) {
            float v = tile[tx][ty + 8*j];
            __nv_bfloat16 h = __float2bfloat16_rn(v);
            __nv_bfloat16 lo = __float2bfloat16_rn(v - __bfloat162float(h));
            int n = n0 + ty + 8*j;
            int nb = n / 96, rb = n - nb * 96;
            uint32_t b = (uint32_t)(rb * 64 + kc * 2);
            uint32_t sw = SWZ(b);
            size_t tb_hi = ((size_t)(nb) * NIT + ch) * BTILE;
            size_t tb_lo = ((size_t)(NNB + nb) * NIT + ch) * BTILE;
            *(__nv_bfloat16*)(g_bt + tb_hi + sw) = h;
            *(__nv_bfloat16*)(g_bt + tb_lo + sw) = lo;
        }
    }
}

// ================ mma.sync bf16-split GEMM =========================
// R12 config (8 warps, warp tile 32x48) + round-robin distributed
// issue: full/empty mbarrier pairs per ring slot; every warp's lane0
// arrives on empty[slot] after its MMAs; warp (it%8) alone waits
// empty and reissues chunk it+3 -> the blocking wait hits each warp
// only every 8th chunk while the other 7 stream on (skew bounded by
// the 3-deep ring). Fixes R14's tid0 serialization.
__global__ __launch_bounds__(256, 2) void gemm_kernel(const float* __restrict__ bias) {
    extern __shared__ char smem[];
    uint32_t sb = smem_to_u32(smem);
    int tid = threadIdx.x, wid = tid >> 5, lane = tid & 31;
    int nblk = blockIdx.x, mblk = blockIdx.y;
    int n0 = nblk * BN, m0 = mblk * BM;

    uint32_t mb_full  = sb + MB_OFF;        // 3 x 8B
    uint32_t mb_empty = sb + MB_OFF + 24;   // 3 x 8B

    if (tid == 0) {
        #pragma unroll
        for (int s = 0; s < NSTAGE; ++s) {
            MBARRIER_INIT(mb_full + s * 8, 1);
            MBARRIER_INIT(mb_empty + s * 8, NWARP);
        }
    }
    __syncthreads();

    auto issue = [&](int ch, int s) {
        uint32_t mb = mb_full + s * 8;
        uint32_t dst = sb + s * STG;
        MBARRIER_EXPECT_TX(mb, STG);
        bulk_g2s(dst,          g_at + ((size_t)(mblk) * NIT + ch) * ATILE,        ATILE, mb);
        bulk_g2s(dst + S_ALO,  g_at + ((size_t)(NMB + mblk) * NIT + ch) * ATILE,  ATILE, mb);
        bulk_g2s(dst + S_BHI,  g_bt + ((size_t)(nblk) * NIT + ch) * BTILE,        BTILE, mb);
        bulk_g2s(dst + S_BLO,  g_bt + ((size_t)(NNB + nblk) * NIT + ch) * BTILE,  BTILE, mb);
    };

    if (tid == 0) { issue(0, 0); issue(1, 1); issue(2, 2); }

    int wm = (wid >> 1) * 32;          // warp m-offset (4m x 2n grid)
    int wn = (wid & 1) * 48;           // warp n-offset

    // per-lane swizzled ldmatrix address components (64B-pitch rows)
    int rA = wm + (lane & 15);
    uint32_t RA0 = (uint32_t)rA * 64,        mA0 = (RA0 >> 3) & 0x30;
    uint32_t RA1 = (uint32_t)(rA + 16) * 64, mA1 = (RA1 >> 3) & 0x30;
    int rB = wn + (lane & 7) + ((lane >> 4) & 1) * 8;
    uint32_t RB0 = (uint32_t)rB * 64,        mB0 = (RB0 >> 3) & 0x30;
    uint32_t RB1 = (uint32_t)(rB + 16) * 64, mB1 = (RB1 >> 3) & 0x30;
    uint32_t RB2 = (uint32_t)(rB + 32) * 64, mB2 = (RB2 >> 3) & 0x30;
    uint32_t colAsel = (uint32_t)(lane >> 4) * 16;
    uint32_t colBsel = (uint32_t)((lane >> 3) & 1) * 16;

    float acc[2][6][4];
    #pragma unroll
    for (int i = 0; i < 2; ++i)
        #pragma unroll
        for (int j = 0; j < 6; ++j)
            #pragma unroll
            for (int q = 0; q < 4; ++q) acc[i][j][q] = 0.f;

    int slot = 0, phase = 0;
    for (int it = 0; it < NIT; ++it) {
        MBARRIER_WAIT_PARITY(mb_full + slot * 8, phase);
        uint32_t base = sb + slot * STG;
        #pragma unroll
        for (int ki = 0; ki < 2; ++ki) {
            uint32_t ah[2][4], al[2][4], bh[6][2], bl[6][2];
            uint32_t cA = (uint32_t)ki * 32 + colAsel;
            uint32_t cB = (uint32_t)ki * 32 + colBsel;
            LDSM_X4(ah[0][0], ah[0][1], ah[0][2], ah[0][3], base + RA0 + (cA ^ mA0));
            LDSM_X4(ah[1][0], ah[1][1], ah[1][2], ah[1][3], base + RA1 + (cA ^ mA1));
            LDSM_X4(al[0][0], al[0][1], al[0][2], al[0][3], base + S_ALO + RA0 + (cA ^ mA0));
            LDSM_X4(al[1][0], al[1][1], al[1][2], al[1][3], base + S_ALO + RA1 + (cA ^ mA1));
            LDSM_X4(bh[0][0], bh[0][1], bh[1][0], bh[1][1], base + S_BHI + RB0 + (cB ^ mB0));
            LDSM_X4(bh[2][0], bh[2][1], bh[3][0], bh[3][1], base + S_BHI + RB1 + (cB ^ mB1));
            LDSM_X4(bh[4][0], bh[4][1], bh[5][0], bh[5][1], base + S_BHI + RB2 + (cB ^ mB2));
            LDSM_X4(bl[0][0], bl[0][1], bl[1][0], bl[1][1], base + S_BLO + RB0 + (cB ^ mB0));
            LDSM_X4(bl[2][0], bl[2][1], bl[3][0], bl[3][1], base + S_BLO + RB1 + (cB ^ mB1));
            LDSM_X4(bl[4][0], bl[4][1], bl[5][0], bl[5][1], base + S_BLO + RB2 + (cB ^ mB2));
            #pragma unroll
            for (int mi = 0; mi < 2; ++mi)
                #pragma unroll
                for (int nj = 0; nj < 6; ++nj)
                    MMA16816(acc[mi][nj], ah[mi], bh[nj]);
            #pragma unroll
            for (int mi = 0; mi < 2; ++mi)
                #pragma unroll
                for (int nj = 0; nj < 6; ++nj)
                    MMA16816(acc[mi][nj], al[mi], bh[nj]);
            #pragma unroll
            for (int mi = 0; mi < 2; ++mi)
                #pragma unroll
                for (int nj = 0; nj < 6; ++nj)
                    MMA16816(acc[mi][nj], ah[mi], bl[nj]);
        }
        if (lane == 0) {
            MBARRIER_ARRIVE(mb_empty + slot * 8);
            if (wid == (it & 7) && it + NSTAGE < NIT) {
                MBARRIER_WAIT_PARITY(mb_empty + slot * 8, phase);  // all 8 warps done
                issue(it + NSTAGE, slot);
            }
        }
        if (++slot == NSTAGE) { slot = 0; phase ^= 1; }
    }

    // ---- epilogue: frags -> g_pT (transposed, +bias) ----
    int qr = lane >> 2, qc = (lane & 3) * 2;
    #pragma unroll
    for (int mi = 0; mi < 2; ++mi) {
        int m = m0 + wm + mi * 16 + qr;
        #pragma unroll
        for (int nj = 0; nj < 6; ++nj) {
            int n = n0 + wn + nj * 8 + qc;
            float b0 = bias[n], b1 = bias[n + 1];
            g_pT[(size_t)n       * SEQ + m]     = acc[mi][nj][0] + b0;
            g_pT[(size_t)(n + 1) * SEQ + m]     = acc[mi][nj][1] + b1;
            g_pT[(size_t)n       * SEQ + m + 8] = acc[mi][nj][2] + b0;
            g_pT[(size_t)(n + 1) * SEQ + m + 8] = acc[mi][nj][3] + b1;
        }
    }
}

// ============== Fused transform + spring scatter (R11) =============
__global__ __launch_bounds__(256) void spring_kernel(float* __restrict__ out) {
    __shared__ float buf[8][336];
    int tid  = threadIdx.x;
    int lane = tid & 31;
    int imu = blockIdx.y;
    int c0  = blockIdx.x * 256;
    int t0  = c0 + tid;

    for (int i = tid; i < 8 * 336; i += 256) ((float*)buf)[i] = 0.f;

    const float* col = g_pT + (size_t)imu * SEQ + t0;
    float p0  = col[0*PLANE],  p1  = col[1*PLANE],  p2  = col[2*PLANE],  p3 = col[3*PLANE];
    float p4  = col[4*PLANE],  p5  = col[5*PLANE],  p6  = col[6*PLANE],  p7 = col[7*PLANE];
    float p8  = col[8*PLANE],  p9  = col[9*PLANE],  p10 = col[10*PLANE], p11 = col[11*PLANE];

    size_t ob = (size_t)imu * SEQ + t0;
    out[1 * PLANE + ob] = p8;
    out[2 * PLANE + ob] = softplusf(p9);
    out[3 * PLANE + ob] = p10;
    out[4 * PLANE + ob] = softplusf(p11);

    float om1 = sqrtf(softplusf(p0));
    float e1  = expf(-0.5f * softplusf(p1));
    float om2 = sqrtf(softplusf(p2));
    float e2  = expf(-0.5f * softplusf(p3));
    float sph1, cph1; sincosf(p6, &sph1, &cph1);
    float sph2, cph2; sincosf(p7, &sph2, &cph2);
    float so1, co1;   sincosf(om1, &so1, &co1);
    float so2, co2;   sincosf(om2, &so2, &co2);

    float r1r = e1 * co1, r1i = e1 * so1;
    float q1r = e2 * co2, q1i = e2 * so2;
    float r2r = r1r*r1r - r1i*r1i, r2i = 2.f*r1r*r1i;
    float q2r = q1r*q1r - q1i*q1i, q2i = 2.f*q1r*q1i;
    float r3r = r2r*r1r - r2i*r1i, r3i = r2r*r1i + r2i*r1r;
    float q3r = q2r*q1r - q2i*q1i, q3i = q2r*q1i + q2i*q1r;
    float r4r = r2r*r2r - r2i*r2i, r4i = 2.f*r2r*r2i;
    float q4r = q2r*q2r - q2i*q2i, q4i = 2.f*q2r*q2i;

    ull P1r = fpack2(r1r, q1r), P1i = fpack2(r1i, q1i);
    ull P2r = fpack2(r2r, q2r), P2i = fpack2(r2i, q2i);
    ull P3r = fpack2(r3r, q3r), P3i = fpack2(r3i, q3i);
    ull P4r = fpack2(r4r, q4r), P4i = fpack2(r4i, q4i);
    ull P4in = fpack2(-r4i, -q4i);

    ull Ur = fpack2(p4 * cph1, p5 * cph2);
    ull Ui = fpack2(p4 * sph1, p5 * sph2);

    __syncthreads();

    volatile float* wb = &buf[tid >> 5][lane];

    #pragma unroll 2
    for (int m = 0; m < TSTEPS / 4; ++m) {
        ull x1 = ffma2(Ur, P1i, fmul2(Ui, P1r));
        ull x2 = ffma2(Ur, P2i, fmul2(Ui, P2r));
        ull x3 = ffma2(Ur, P3i, fmul2(Ui, P3r));
        float2 a0 = funpack2(Ui);
        float2 a1 = funpack2(x1);
        float2 a2 = funpack2(x2);
        float2 a3 = funpack2(x3);
        ull t1 = fmul2(Ui, P4in);
        ull t2 = fmul2(Ui, P4r);
        ull nUr = ffma2(Ur, P4r, t1);
        ull nUi = ffma2(Ur, P4i, t2);
        Ur = nUr; Ui = nUi;
        int base = 4 * m;
        wb[base + 0] = wb[base + 0] + (a0.x + a0.y);
        wb[base + 1] = wb[base + 1] + (a1.x + a1.y);
        wb[base + 2] = wb[base + 2] + (a2.x + a2.y);
        wb[base + 3] = wb[base + 3] + (a3.x + a3.y);
    }
    __syncthreads();

    for (int o = tid; o < 555; o += 256) {
        float v = 0.f;
        #pragma unroll
        for (int w = 0; w < 8; ++w) {
            int idx = o - (w << 5);
            if (idx >= 0 && idx <= 330) v += buf[w][idx];
        }
        int pos = c0 + o;
        if (pos < SEQ) atomicAdd(out + (size_t)imu * SEQ + pos, v);
    }
}

// =========================== launch ================================
extern "C" void kernel_launch(void* const* d_in, const int* in_sizes, int n_in,
                              void* d_out, int out_size) {
    const float* hs    = (const float*)d_in[0];
    const float* gamma = (const float*)d_in[1];
    const float* beta  = (const float*)d_in[2];
    const float* W     = (const float*)d_in[3];
    const float* b     = (const float*)d_in[4];
    float* out = (float*)d_out;

    cudaFuncSetAttribute(gemm_kernel, cudaFuncAttributeMaxDynamicSharedMemorySize, SMEM_TOT);

    zero_kernel<<<PLANE / 2048, 256>>>(out);                        // #1 (first half)
    zero_kernel<<<PLANE / 2048, 256>>>(out + PLANE / 2);            // #2 (second half)
    prep_kernel<<<SEQ + 864, 256>>>(hs, gamma, beta, W);            // #3 (LN + W^T, tiled)
    gemm_kernel<<<dim3(NNB, NMB), 256, SMEM_TOT>>>(b);              // #4 (ncu target)
    spring_kernel<<<dim3(SEQ / 256, NIMU), 256>>>(out);             // #5
}

// round 16
// speedup vs baseline: 1.0678x; 1.0678x over previous
#include <cuda_runtime.h>
#include <cuda_bf16.h>
#include <cstdint>

#define SEQ    4096
#define DM     1024
#define NOUT   864      // 12 * 72
#define NIMU   72
#define TSTEPS 300
#define PLANE  (NIMU*SEQ)   // 294912

// GEMM tiling (mma.sync m16n8k16 bf16), bulk-copy staging (R12 config)
#define BM     128
#define BN     96
#define BK     32
#define NIT    (DM/BK)        // 32 k-chunks
#define NMB    (SEQ/BM)       // 32 m-blocks
#define NNB    (NOUT/BN)      // 9  n-blocks
#define ATILE  8192           // 128 rows x 64B
#define BTILE  6144           // 96 rows x 64B
#define STG    28672          // ahi+alo+bhi+blo per chunk
#define S_ALO  8192
#define S_BHI  16384
#define S_BLO  22528
#define NSTAGE 3
#define MB_OFF (NSTAGE*STG)               // 86016
#define SMEM_TOT (NSTAGE*STG + 64)        // 86080 -> 2 CTAs/SM

// prep grid layout: [0,SEQ) LN rows, [SEQ,SEQ+864) W tiles, rest zero-out
#define PREP_W_BLKS 864
#define PREP_Z_BLKS (PLANE / 1024)        // 288 blocks x 256 thr x float4
#define PREP_GRID   (SEQ + PREP_W_BLKS + PREP_Z_BLKS)

typedef unsigned long long ull;

// -------- scratch: tiled+swizzled chunk layouts (bulk-copy sources) ----
// A: [mat(2)][mblk(32)][chunk(32)][128 rows x 64B]   (16 MB)
// B: [mat(2)][nblk(9)][chunk(32)][96 rows x 64B]     (3.5 MB)
__device__ __align__(16) char g_at[2 * NMB * NIT * ATILE];
__device__ __align__(16) char g_bt[2 * NNB * NIT * BTILE];
__device__ __align__(16) float g_pT[NOUT * SEQ];   // GEMM out, TRANSPOSED [n][s]

// SW64-ish swizzle on 64B-pitch rows: bits[5:4] ^= bits[8:7]
#define SWZ(b) ((b) ^ (((b) >> 3) & 0x30))

// ======================= PTX helpers ===============================
__device__ __forceinline__ uint32_t smem_to_u32(const void* p) {
    uint32_t a;
    asm("{ .reg .u64 t; cvta.to.shared.u64 t, %1; cvt.u32.u64 %0, t; }" : "=r"(a) : "l"(p));
    return a;
}
#define MBARRIER_INIT(mb, cnt) \
    asm volatile("mbarrier.init.shared.b64 [%0], %1;" :: "r"((uint32_t)(mb)), "r"((uint32_t)(cnt)) : "memory")
#define MBARRIER_EXPECT_TX(mb, tx) \
    asm volatile("mbarrier.arrive.expect_tx.shared.b64 _, [%0], %1;" \
                 :: "r"((uint32_t)(mb)), "r"((uint32_t)(tx)) : "memory")
#define MBARRIER_WAIT_PARITY(mb, par) do { \
    uint32_t _m = (uint32_t)(mb), _p = (uint32_t)(par), _d; \
    asm volatile("{\n\t.reg .pred p;\n\tmbarrier.try_wait.parity.acquire.cta.shared::cta.b64 p, [%1], %2;\n\tselp.b32 %0, 1, 0, p;\n\t}" \
                 : "=r"(_d) : "r"(_m), "r"(_p) : "memory"); \
    if (!_d) { \
        asm volatile("{\n\t.reg .pred P1;\n\tWL_%=:\n\tmbarrier.try_wait.parity.acquire.cta.shared::cta.b64 P1, [%0], %1, 0x989680;\n\t@P1 bra.uni WD_%=;\n\tbra.uni WL_%=;\n\tWD_%=:\n\t}" \
                     :: "r"(_m), "r"(_p) : "memory"); \
    } } while (0)
__device__ __forceinline__ void bulk_g2s(uint32_t dst, const void* src, uint32_t bytes,
                                         uint32_t mbar) {
    asm volatile("cp.async.bulk.shared::cluster.global.mbarrier::complete_tx::bytes "
                 "[%0], [%1], %2, [%3];"
                 :: "r"(dst), "l"(src), "r"(bytes), "r"(mbar) : "memory");
}
#define LDSM_X4(r0, r1, r2, r3, addr) \
    asm volatile("ldmatrix.sync.aligned.m8n8.x4.shared.b16 {%0,%1,%2,%3}, [%4];" \
                 : "=r"(r0), "=r"(r1), "=r"(r2), "=r"(r3) : "r"(addr))
#define MMA16816(d, a, b) \
    asm volatile("mma.sync.aligned.m16n8k16.row.col.f32.bf16.bf16.f32 " \
                 "{%0,%1,%2,%3}, {%4,%5,%6,%7}, {%8,%9}, {%0,%1,%2,%3};" \
                 : "+f"((d)[0]), "+f"((d)[1]), "+f"((d)[2]), "+f"((d)[3]) \
                 : "r"((a)[0]), "r"((a)[1]), "r"((a)[2]), "r"((a)[3]), \
                   "r"((b)[0]), "r"((b)[1]))

__device__ __forceinline__ ull ffma2(ull a, ull b, ull c) {
    ull d; asm("fma.rn.f32x2 %0, %1, %2, %3;" : "=l"(d) : "l"(a), "l"(b), "l"(c)); return d;
}
__device__ __forceinline__ ull fmul2(ull a, ull b) {
    ull d; asm("mul.rn.f32x2 %0, %1, %2;" : "=l"(d) : "l"(a), "l"(b)); return d;
}
__device__ __forceinline__ ull fpack2(float lo, float hi) {
    ull d; asm("mov.b64 %0, {%1, %2};" : "=l"(d) : "f"(lo), "f"(hi)); return d;
}
__device__ __forceinline__ float2 funpack2(ull v) {
    float lo, hi; asm("mov.b64 {%0, %1}, %2;" : "=f"(lo), "=f"(hi) : "l"(v));
    return make_float2(lo, hi);
}
__device__ __forceinline__ float softplusf(float x) {
    return fmaxf(x, 0.0f) + log1pf(expf(-fabsf(x)));
}
__device__ __forceinline__ uint32_t bf2u(__nv_bfloat16 a, __nv_bfloat16 b) {
    __nv_bfloat162 v; v.x = a; v.y = b;
    return *reinterpret_cast<uint32_t*>(&v);
}

// ====== Fused LayerNorm + W-transpose + kinematics zeroing =========
// blocks [0, SEQ): LN row -> bf16 hi/lo splits into tiled layout
// blocks [SEQ, SEQ+864): 32x32 W transpose tiles -> tiled layout
// blocks [SEQ+864, ...): zero out[0..PLANE) (kinematics accumulator)
__global__ __launch_bounds__(256) void prep_kernel(const float* __restrict__ hs,
                                                   const float* __restrict__ gamma,
                                                   const float* __restrict__ beta,
                                                   const float* __restrict__ W,
                                                   float* __restrict__ out) {
    int tid = threadIdx.x;
    if (blockIdx.x < SEQ) {
        int row = blockIdx.x;
        const float4* xr = (const float4*)(hs + (size_t)row * DM);
        float4 v = xr[tid];
        float s  = v.x + v.y + v.z + v.w;
        float ss = v.x*v.x + v.y*v.y + v.z*v.z + v.w*v.w;
        #pragma unroll
        for (int o = 16; o > 0; o >>= 1) {
            s  += __shfl_xor_sync(0xffffffffu, s,  o);
            ss += __shfl_xor_sync(0xffffffffu, ss, o);
        }
        __shared__ float2 part[8];
        __shared__ float2 mv;
        int w = tid >> 5, l = tid & 31;
        if (l == 0) part[w] = make_float2(s, ss);
        __syncthreads();
        if (tid == 0) {
            float S = 0.f, SS = 0.f;
            #pragma unroll
            for (int i = 0; i < 8; ++i) { S += part[i].x; SS += part[i].y; }
            float mu  = S * (1.0f / DM);
            float var = SS * (1.0f / DM) - mu * mu;
            mv = make_float2(mu, rsqrtf(var + 1e-5f));
        }
        __syncthreads();
        float mu = mv.x, rstd = mv.y;
        float4 g  = ((const float4*)gamma)[tid];
        float4 be = ((const float4*)beta)[tid];
        float o0 = (v.x - mu) * rstd * g.x + be.x;
        float o1 = (v.y - mu) * rstd * g.y + be.y;
        float o2 = (v.z - mu) * rstd * g.z + be.z;
        float o3 = (v.w - mu) * rstd * g.w + be.w;

        __nv_bfloat16 h0 = __float2bfloat16_rn(o0), h1 = __float2bfloat16_rn(o1);
        __nv_bfloat16 h2 = __float2bfloat16_rn(o2), h3 = __float2bfloat16_rn(o3);
        __nv_bfloat16 l0 = __float2bfloat16_rn(o0 - __bfloat162float(h0));
        __nv_bfloat16 l1 = __float2bfloat16_rn(o1 - __bfloat162float(h1));
        __nv_bfloat16 l2 = __float2bfloat16_rn(o2 - __bfloat162float(h2));
        __nv_bfloat16 l3 = __float2bfloat16_rn(o3 - __bfloat162float(h3));

        // tiled write: k = 4*tid; chunk = tid>>3; 8 bytes at swizzled slot
        int mb = row >> 7, r = row & 127;
        int ch = tid >> 3;
        uint32_t b = (uint32_t)(r * 64 + (tid & 7) * 8);
        uint32_t sw = SWZ(b);
        size_t tb_hi = ((size_t)(mb) * NIT + ch) * ATILE;
        size_t tb_lo = ((size_t)(NMB + mb) * NIT + ch) * ATILE;
        ull hv = ((ull)bf2u(h2, h3) << 32) | bf2u(h0, h1);
        ull lv = ((ull)bf2u(l2, l3) << 32) | bf2u(l0, l1);
        *(ull*)(g_at + tb_hi + sw) = hv;
        *(ull*)(g_at + tb_lo + sw) = lv;
    } else if (blockIdx.x < SEQ + PREP_W_BLKS) {
        __shared__ float tile[32][33];
        int b2 = blockIdx.x - SEQ;                 // 0..863 (27 x 32 tiles)
        int n0 = (b2 % 27) * 32, k0 = (b2 / 27) * 32;
        int tx = tid & 31, ty = tid >> 5;          // 32 x 8
        #pragma unroll
        for (int j = 0; j < 4; ++j)
            tile[ty + 8*j][tx] = W[(size_t)(k0 + ty + 8*j) * NOUT + n0 + tx];
        __syncthreads();
        int ch = (k0 + tx) >> 5;
        int kc = (k0 + tx) & 31;
        #pragma unroll
        for (int j = 0; j < 4; ++j) {
            float v = tile[tx][ty + 8*j];
            __nv_bfloat16 h = __float2bfloat16_rn(v);
            __nv_bfloat16 lo = __float2bfloat16_rn(v - __bfloat162float(h));
            int n = n0 + ty + 8*j;
            int nb = n / 96, rb = n - nb * 96;
            uint32_t b = (uint32_t)(rb * 64 + kc * 2);
            uint32_t sw = SWZ(b);
            size_t tb_hi = ((size_t)(nb) * NIT + ch) * BTILE;
            size_t tb_lo = ((size_t)(NNB + nb) * NIT + ch) * BTILE;
            *(__nv_bfloat16*)(g_bt + tb_hi + sw) = h;
            *(__nv_bfloat16*)(g_bt + tb_lo + sw) = lo;
        }
    } else {
        int zb = blockIdx.x - SEQ - PREP_W_BLKS;   // 0..287
        int i = zb * 256 + tid;                    // float4 index into out[0..PLANE)
        ((float4*)out)[i] = make_float4(0.f, 0.f, 0.f, 0.f);
    }
}

// ================ mma.sync bf16-split GEMM (R12, banked) ===========
// Staging: 4 cp.async.bulk per chunk (one thread) + mbarrier ring.
// Compute: 8 warps 4m x 2n, warp tile 32x48, product-major; one
// __syncthreads per chunk. Measured 48.3us / tensor 72.7% — best of
// all sync variants (R13 occupancy, R14/R15 mbarrier pipelines lost).
__global__ __launch_bounds__(256, 2) void gemm_kernel(const float* __restrict__ bias) {
    extern __shared__ char smem[];
    uint32_t sb = smem_to_u32(smem);
    int tid = threadIdx.x, wid = tid >> 5, lane = tid & 31;
    int nblk = blockIdx.x, mblk = blockIdx.y;
    int n0 = nblk * BN, m0 = mblk * BM;

    if (tid == 0) {
        #pragma unroll
        for (int s = 0; s < NSTAGE; ++s) MBARRIER_INIT(sb + MB_OFF + s * 8, 1);
    }
    __syncthreads();

    auto issue = [&](int ch, int s) {
        if (tid == 0) {
            uint32_t mb = sb + MB_OFF + s * 8;
            uint32_t dst = sb + s * STG;
            MBARRIER_EXPECT_TX(mb, STG);
            bulk_g2s(dst,          g_at + ((size_t)(mblk) * NIT + ch) * ATILE,        ATILE, mb);
            bulk_g2s(dst + S_ALO,  g_at + ((size_t)(NMB + mblk) * NIT + ch) * ATILE,  ATILE, mb);
            bulk_g2s(dst + S_BHI,  g_bt + ((size_t)(nblk) * NIT + ch) * BTILE,        BTILE, mb);
            bulk_g2s(dst + S_BLO,  g_bt + ((size_t)(NNB + nblk) * NIT + ch) * BTILE,  BTILE, mb);
        }
    };

    issue(0, 0); issue(1, 1); issue(2, 2);

    int wm = (wid >> 1) * 32;          // warp m-offset (4m x 2n grid)
    int wn = (wid & 1) * 48;           // warp n-offset

    // per-lane swizzled ldmatrix address components (64B-pitch rows)
    int rA = wm + (lane & 15);
    uint32_t RA0 = (uint32_t)rA * 64,        mA0 = (RA0 >> 3) & 0x30;
    uint32_t RA1 = (uint32_t)(rA + 16) * 64, mA1 = (RA1 >> 3) & 0x30;
    int rB = wn + (lane & 7) + ((lane >> 4) & 1) * 8;
    uint32_t RB0 = (uint32_t)rB * 64,        mB0 = (RB0 >> 3) & 0x30;
    uint32_t RB1 = (uint32_t)(rB + 16) * 64, mB1 = (RB1 >> 3) & 0x30;
    uint32_t RB2 = (uint32_t)(rB + 32) * 64, mB2 = (RB2 >> 3) & 0x30;
    uint32_t colAsel = (uint32_t)(lane >> 4) * 16;
    uint32_t colBsel = (uint32_t)((lane >> 3) & 1) * 16;

    float acc[2][6][4];
    #pragma unroll
    for (int i = 0; i < 2; ++i)
        #pragma unroll
        for (int j = 0; j < 6; ++j)
            #pragma unroll
            for (int q = 0; q < 4; ++q) acc[i][j][q] = 0.f;

    int slot = 0, phase = 0;
    for (int it = 0; it < NIT; ++it) {
        MBARRIER_WAIT_PARITY(sb + MB_OFF + slot * 8, phase);
        uint32_t base = sb + slot * STG;
        #pragma unroll
        for (int ki = 0; ki < 2; ++ki) {
            uint32_t ah[2][4], al[2][4], bh[6][2], bl[6][2];
            uint32_t cA = (uint32_t)ki * 32 + colAsel;
            uint32_t cB = (uint32_t)ki * 32 + colBsel;
            LDSM_X4(ah[0][0], ah[0][1], ah[0][2], ah[0][3], base + RA0 + (cA ^ mA0));
            LDSM_X4(ah[1][0], ah[1][1], ah[1][2], ah[1][3], base + RA1 + (cA ^ mA1));
            LDSM_X4(al[0][0], al[0][1], al[0][2], al[0][3], base + S_ALO + RA0 + (cA ^ mA0));
            LDSM_X4(al[1][0], al[1][1], al[1][2], al[1][3], base + S_ALO + RA1 + (cA ^ mA1));
            LDSM_X4(bh[0][0], bh[0][1], bh[1][0], bh[1][1], base + S_BHI + RB0 + (cB ^ mB0));
            LDSM_X4(bh[2][0], bh[2][1], bh[3][0], bh[3][1], base + S_BHI + RB1 + (cB ^ mB1));
            LDSM_X4(bh[4][0], bh[4][1], bh[5][0], bh[5][1], base + S_BHI + RB2 + (cB ^ mB2));
            LDSM_X4(bl[0][0], bl[0][1], bl[1][0], bl[1][1], base + S_BLO + RB0 + (cB ^ mB0));
            LDSM_X4(bl[2][0], bl[2][1], bl[3][0], bl[3][1], base + S_BLO + RB1 + (cB ^ mB1));
            LDSM_X4(bl[4][0], bl[4][1], bl[5][0], bl[5][1], base + S_BLO + RB2 + (cB ^ mB2));
            #pragma unroll
            for (int mi = 0; mi < 2; ++mi)
                #pragma unroll
                for (int nj = 0; nj < 6; ++nj)
                    MMA16816(acc[mi][nj], ah[mi], bh[nj]);
            #pragma unroll
            for (int mi = 0; mi < 2; ++mi)
                #pragma unroll
                for (int nj = 0; nj < 6; ++nj)
                    MMA16816(acc[mi][nj], al[mi], bh[nj]);
            #pragma unroll
            for (int mi = 0; mi < 2; ++mi)
                #pragma unroll
                for (int nj = 0; nj < 6; ++nj)
                    MMA16816(acc[mi][nj], ah[mi], bl[nj]);
        }
        __syncthreads();                       // all warps done with this slot
        if (it + NSTAGE < NIT) issue(it + NSTAGE, slot);
        if (++slot == NSTAGE) { slot = 0; phase ^= 1; }
    }

    // ---- epilogue: frags -> g_pT (transposed, +bias) ----
    int qr = lane >> 2, qc = (lane & 3) * 2;
    #pragma unroll
    for (int mi = 0; mi < 2; ++mi) {
        int m = m0 + wm + mi * 16 + qr;
        #pragma unroll
        for (int nj = 0; nj < 6; ++nj) {
            int n = n0 + wn + nj * 8 + qc;
            float b0 = bias[n], b1 = bias[n + 1];
            g_pT[(size_t)n       * SEQ + m]     = acc[mi][nj][0] + b0;
            g_pT[(size_t)(n + 1) * SEQ + m]     = acc[mi][nj][1] + b1;
            g_pT[(size_t)n       * SEQ + m + 8] = acc[mi][nj][2] + b0;
            g_pT[(size_t)(n + 1) * SEQ + m + 8] = acc[mi][nj][3] + b1;
        }
    }
}

// ============== Fused transform + spring scatter (R11) =============
// k=4 step-combined recurrence + scalar volatile smem RMW slots.
__global__ __launch_bounds__(256) void spring_kernel(float* __restrict__ out) {
    __shared__ float buf[8][336];
    int tid  = threadIdx.x;
    int lane = tid & 31;
    int imu = blockIdx.y;
    int c0  = blockIdx.x * 256;
    int t0  = c0 + tid;

    for (int i = tid; i < 8 * 336; i += 256) ((float*)buf)[i] = 0.f;

    const float* col = g_pT + (size_t)imu * SEQ + t0;
    float p0  = col[0*PLANE],  p1  = col[1*PLANE],  p2  = col[2*PLANE],  p3 = col[3*PLANE];
    float p4  = col[4*PLANE],  p5  = col[5*PLANE],  p6  = col[6*PLANE],  p7 = col[7*PLANE];
    float p8  = col[8*PLANE],  p9  = col[9*PLANE],  p10 = col[10*PLANE], p11 = col[11*PLANE];

    size_t ob = (size_t)imu * SEQ + t0;
    out[1 * PLANE + ob] = p8;
    out[2 * PLANE + ob] = softplusf(p9);
    out[3 * PLANE + ob] = p10;
    out[4 * PLANE + ob] = softplusf(p11);

    float om1 = sqrtf(softplusf(p0));
    float e1  = expf(-0.5f * softplusf(p1));
    float om2 = sqrtf(softplusf(p2));
    float e2  = expf(-0.5f * softplusf(p3));
    float sph1, cph1; sincosf(p6, &sph1, &cph1);
    float sph2, cph2; sincosf(p7, &sph2, &cph2);
    float so1, co1;   sincosf(om1, &so1, &co1);
    float so2, co2;   sincosf(om2, &so2, &co2);

    float r1r = e1 * co1, r1i = e1 * so1;
    float q1r = e2 * co2, q1i = e2 * so2;
    float r2r = r1r*r1r - r1i*r1i, r2i = 2.f*r1r*r1i;
    float q2r = q1r*q1r - q1i*q1i, q2i = 2.f*q1r*q1i;
    float r3r = r2r*r1r - r2i*r1i, r3i = r2r*r1i + r2i*r1r;
    float q3r = q2r*q1r - q2i*q1i, q3i = q2r*q1i + q2i*q1r;
    float r4r = r2r*r2r - r2i*r2i, r4i = 2.f*r2r*r2i;
    float q4r = q2r*q2r - q2i*q2i, q4i = 2.f*q2r*q2i;

    ull P1r = fpack2(r1r, q1r), P1i = fpack2(r1i, q1i);
    ull P2r = fpack2(r2r, q2r), P2i = fpack2(r2i, q2i);
    ull P3r = fpack2(r3r, q3r), P3i = fpack2(r3i, q3i);
    ull P4r = fpack2(r4r, q4r), P4i = fpack2(r4i, q4i);
    ull P4in = fpack2(-r4i, -q4i);

    ull Ur = fpack2(p4 * cph1, p5 * cph2);
    ull Ui = fpack2(p4 * sph1, p5 * sph2);

    __syncthreads();

    volatile float* wb = &buf[tid >> 5][lane];

    #pragma unroll 2
    for (int m = 0; m < TSTEPS / 4; ++m) {
        ull x1 = ffma2(Ur, P1i, fmul2(Ui, P1r));
        ull x2 = ffma2(Ur, P2i, fmul2(Ui, P2r));
        ull x3 = ffma2(Ur, P3i, fmul2(Ui, P3r));
        float2 a0 = funpack2(Ui);
        float2 a1 = funpack2(x1);
        float2 a2 = funpack2(x2);
        float2 a3 = funpack2(x3);
        ull t1 = fmul2(Ui, P4in);
        ull t2 = fmul2(Ui, P4r);
        ull nUr = ffma2(Ur, P4r, t1);
        ull nUi = ffma2(Ur, P4i, t2);
        Ur = nUr; Ui = nUi;
        int base = 4 * m;
        wb[base + 0] = wb[base + 0] + (a0.x + a0.y);
        wb[base + 1] = wb[base + 1] + (a1.x + a1.y);
        wb[base + 2] = wb[base + 2] + (a2.x + a2.y);
        wb[base + 3] = wb[base + 3] + (a3.x + a3.y);
    }
    __syncthreads();

    for (int o = tid; o < 555; o += 256) {
        float v = 0.f;
        #pragma unroll
        for (int w = 0; w < 8; ++w) {
            int idx = o - (w << 5);
            if (idx >= 0 && idx <= 330) v += buf[w][idx];
        }
        int pos = c0 + o;
        if (pos < SEQ) atomicAdd(out + (size_t)imu * SEQ + pos, v);
    }
}

// =========================== launch ================================
extern "C" void kernel_launch(void* const* d_in, const int* in_sizes, int n_in,
                              void* d_out, int out_size) {
    const float* hs    = (const float*)d_in[0];
    const float* gamma = (const float*)d_in[1];
    const float* beta  = (const float*)d_in[2];
    const float* W     = (const float*)d_in[3];
    const float* b     = (const float*)d_in[4];
    float* out = (float*)d_out;

    cudaFuncSetAttribute(gemm_kernel, cudaFuncAttributeMaxDynamicSharedMemorySize, SMEM_TOT);

    prep_kernel<<<PREP_GRID, 256>>>(hs, gamma, beta, W, out);   // #1 (LN + W^T + zero)
    gemm_kernel<<<dim3(NNB, NMB), 256, SMEM_TOT>>>(b);          // #2
    spring_kernel<<<dim3(SEQ / 256, NIMU), 256>>>(out);         // #3
}